// round 1
// baseline (speedup 1.0000x reference)
#include <cuda_runtime.h>
#include <cuda_bf16.h>
#include <math.h>

// Problem constants (fixed by the dataset)
#define NN      128000      // nodes = B*NG
#define EE      4096000     // edges = B*EG
#define BB      64          // graphs
#define NG      2000        // nodes per graph
#define KTOP    1600
#define EMB     64
#define G1      32
#define G2      32
#define DENSE   64
#define NCLS    10

// ---------------- device scratch (no allocations allowed) ----------------
__device__ int   g_deg[NN];
__device__ int   g_partial[NN];
__device__ int   g_bsum[256];
__device__ int   g_bbase[256];
__device__ int   g_off[NN + 1];
__device__ int   g_cur[NN];
__device__ int   g_csr[EE];
__device__ float g_dinv[NN];
__device__ float g_bufA[NN * 32];
__device__ float g_bufB[NN * 32];
__device__ float g_score[NN];

// ---------------- CSR build ----------------
__global__ void k_zero_deg() {
    int i = blockIdx.x * blockDim.x + threadIdx.x;
    if (i < NN) g_deg[i] = 0;
}

__global__ void k_count_deg(const int* __restrict__ ei) {
    int e = blockIdx.x * blockDim.x + threadIdx.x;
    if (e < EE) atomicAdd(&g_deg[ei[EE + e]], 1);
}

// block-level exclusive scan (1024 elems/block, 125 blocks exactly)
__global__ void k_scan1() {
    __shared__ int s[1024];
    int tid = threadIdx.x;
    int gid = blockIdx.x * 1024 + tid;
    int v = (gid < NN) ? g_deg[gid] : 0;
    int sum = v;
    s[tid] = sum;
    __syncthreads();
    for (int off = 1; off < 1024; off <<= 1) {
        int t = (tid >= off) ? s[tid - off] : 0;
        __syncthreads();
        sum += t;
        s[tid] = sum;
        __syncthreads();
    }
    if (gid < NN) g_partial[gid] = sum - v;     // exclusive
    if (tid == 1023) g_bsum[blockIdx.x] = sum;  // block total
}

__global__ void k_scan2(int nblocks) {          // single block, 128 threads
    __shared__ int s[128];
    int tid = threadIdx.x;
    int v = (tid < nblocks) ? g_bsum[tid] : 0;
    int sum = v;
    s[tid] = sum;
    __syncthreads();
    for (int off = 1; off < 128; off <<= 1) {
        int t = (tid >= off) ? s[tid - off] : 0;
        __syncthreads();
        sum += t;
        s[tid] = sum;
        __syncthreads();
    }
    if (tid < nblocks) g_bbase[tid] = sum - v;  // exclusive
}

__global__ void k_finalize() {
    int i = blockIdx.x * blockDim.x + threadIdx.x;
    if (i < NN) {
        int o = g_partial[i] + g_bbase[i >> 10];
        g_off[i] = o;
        g_cur[i] = o;
        g_dinv[i] = rsqrtf((float)(g_deg[i] + 1));  // +1 self loop
    }
    if (i == 0) g_off[NN] = EE;
}

__global__ void k_csr_fill(const int* __restrict__ ei) {
    int e = blockIdx.x * blockDim.x + threadIdx.x;
    if (e < EE) {
        int src = ei[e];
        int dst = ei[EE + e];
        int pos = atomicAdd(&g_cur[dst], 1);
        g_csr[pos] = src;
    }
}

// ---------------- projection kernels (premultiplied by dinv) ----------------
// hwA[n][j] = dinv[n] * sum_k emb[x[n]][k] * W1[k][j]    (64 -> 32)
__global__ void k_proj1(const int* __restrict__ x, const float* __restrict__ emb,
                        const float* __restrict__ W1) {
    __shared__ float Ws[64 * 32];
    int tid = threadIdx.x;
    for (int i = tid; i < 64 * 32; i += blockDim.x) Ws[i] = W1[i];
    __syncthreads();
    int warp = (blockIdx.x * blockDim.x + tid) >> 5;
    int lane = tid & 31;
    if (warp >= NN) return;
    int xi = x[warp];
    const float* er = emb + (long long)xi * 64;
    float e0 = er[lane];
    float e1 = er[32 + lane];
    float acc = 0.f;
#pragma unroll
    for (int k = 0; k < 32; k++)
        acc += __shfl_sync(0xffffffffu, e0, k) * Ws[k * 32 + lane];
#pragma unroll
    for (int k = 0; k < 32; k++)
        acc += __shfl_sync(0xffffffffu, e1, k) * Ws[(32 + k) * 32 + lane];
    g_bufA[warp * 32 + lane] = acc * g_dinv[warp];
}

// hwA[n][j] = dinv[n] * sum_k h1B[n][k] * W2[k][j]    (32 -> 32)
__global__ void k_proj2(const float* __restrict__ W2) {
    __shared__ float Ws[32 * 32];
    int tid = threadIdx.x;
    for (int i = tid; i < 32 * 32; i += blockDim.x) Ws[i] = W2[i];
    __syncthreads();
    int warp = (blockIdx.x * blockDim.x + tid) >> 5;
    int lane = tid & 31;
    if (warp >= NN) return;
    float h = g_bufB[warp * 32 + lane];
    float acc = 0.f;
#pragma unroll
    for (int k = 0; k < 32; k++)
        acc += __shfl_sync(0xffffffffu, h, k) * Ws[k * 32 + lane];
    g_bufA[warp * 32 + lane] = acc * g_dinv[warp];
}

// ---------------- aggregation: bufB[d] = relu(dinv[d]*(bufA[d] + sum_nbr bufA[s]) + bias) ----------------
// layer2 additionally computes score[d] = tanh(dot(h, pool_w)/||pool_w||)
__global__ void k_agg(const float* __restrict__ bias, const float* __restrict__ pool_w,
                      int layer2) {
    int warp = (blockIdx.x * blockDim.x + threadIdx.x) >> 5;
    int lane = threadIdx.x & 31;
    if (warp >= NN) return;
    int d = warp;
    float a0 = g_bufA[d * 32 + lane];  // self-loop term (already * dinv[d])
    float a1 = 0.f, a2 = 0.f, a3 = 0.f;
    int s0 = g_off[d], s1 = g_off[d + 1];
    int base = s0;
    for (; base + 32 <= s1; base += 32) {
        int sidx = g_csr[base + lane];
#pragma unroll
        for (int k = 0; k < 32; k += 4) {
            int i0 = __shfl_sync(0xffffffffu, sidx, k);
            int i1 = __shfl_sync(0xffffffffu, sidx, k + 1);
            int i2 = __shfl_sync(0xffffffffu, sidx, k + 2);
            int i3 = __shfl_sync(0xffffffffu, sidx, k + 3);
            a0 += g_bufA[i0 * 32 + lane];
            a1 += g_bufA[i1 * 32 + lane];
            a2 += g_bufA[i2 * 32 + lane];
            a3 += g_bufA[i3 * 32 + lane];
        }
    }
    if (base < s1) {
        int cnt = s1 - base;
        int sidx = (base + lane < s1) ? g_csr[base + lane] : 0;
        for (int k = 0; k < cnt; k++) {
            int s = __shfl_sync(0xffffffffu, sidx, k);
            a0 += g_bufA[s * 32 + lane];
        }
    }
    float acc = (a0 + a1) + (a2 + a3);
    float v = fmaxf(acc * g_dinv[d] + bias[lane], 0.f);
    g_bufB[d * 32 + lane] = v;
    if (layer2) {
        float pw = pool_w[lane];
        float s = v * pw;
        float n2 = pw * pw;
#pragma unroll
        for (int off = 16; off; off >>= 1) {
            s  += __shfl_xor_sync(0xffffffffu, s, off);
            n2 += __shfl_xor_sync(0xffffffffu, n2, off);
        }
        if (lane == 0) g_score[d] = tanhf(s * rsqrtf(n2));
    }
}

// ---------------- per-graph top-K + gather-max + MLP head ----------------
__global__ void k_topk_head(const float* __restrict__ dense_W, const float* __restrict__ dense_b,
                            const float* __restrict__ out_W, const float* __restrict__ out_b,
                            float* __restrict__ out) {
    __shared__ unsigned long long keys[2048];
    __shared__ float red[32 * 33];
    __shared__ float gv[32];
    __shared__ float dv[64];
    int b = blockIdx.x;
    int tid = threadIdx.x;  // 1024 threads

    // pack keys: (monotone(score) << 32) | (0xFFFFFFFF - idx)  -> ascending sort,
    // top-K at the tail; ties prefer smaller idx (matches jax.top_k semantics).
    for (int i = tid; i < 2048; i += 1024) {
        unsigned long long key = 0ull;
        if (i < NG) {
            unsigned u = __float_as_uint(g_score[b * NG + i]);
            u = (u & 0x80000000u) ? ~u : (u | 0x80000000u);
            key = ((unsigned long long)u << 32) | (unsigned long long)(0xFFFFFFFFu - (unsigned)i);
        }
        keys[i] = key;
    }
    __syncthreads();

    // bitonic sort, ascending
    for (int k = 2; k <= 2048; k <<= 1) {
        for (int j = k >> 1; j > 0; j >>= 1) {
            for (int i = tid; i < 2048; i += 1024) {
                int ixj = i ^ j;
                if (ixj > i) {
                    bool up = ((i & k) == 0);
                    unsigned long long a = keys[i], c = keys[ixj];
                    if ((a > c) == up) { keys[i] = c; keys[ixj] = a; }
                }
            }
            __syncthreads();
        }
    }

    // top 1600 live at [448, 2048); gv[j] = max over selected of h2[idx][j]*val
    int j = tid & 31, c = tid >> 5;
    float m = -INFINITY;
    for (int t = c; t < KTOP; t += 32) {
        unsigned long long key = keys[448 + t];
        unsigned up = (unsigned)(key >> 32);
        float val = (up & 0x80000000u) ? __uint_as_float(up ^ 0x80000000u)
                                       : __uint_as_float(~up);
        int idx = (int)(0xFFFFFFFFu - (unsigned)key);
        m = fmaxf(m, g_bufB[(b * NG + idx) * 32 + j] * val);
    }
    red[c * 33 + j] = m;
    __syncthreads();
    if (c == 0) {
        for (int cc = 1; cc < 32; cc++) m = fmaxf(m, red[cc * 33 + j]);
        gv[j] = m;
    }
    __syncthreads();
    if (tid < DENSE) {
        float s = dense_b[tid];
#pragma unroll
        for (int k = 0; k < G2; k++) s += gv[k] * dense_W[k * DENSE + tid];
        dv[tid] = fmaxf(s, 0.f);
    }
    __syncthreads();
    if (tid < NCLS) {
        float s = out_b[tid];
#pragma unroll
        for (int k = 0; k < DENSE; k++) s += dv[k] * out_W[k * NCLS + tid];
        out[b * NCLS + tid] = s;
    }
}

// ---------------- launch ----------------
extern "C" void kernel_launch(void* const* d_in, const int* in_sizes, int n_in,
                              void* d_out, int out_size) {
    const int*   x       = (const int*)d_in[0];
    const int*   ei      = (const int*)d_in[1];
    // d_in[2] = batch (unused)
    const float* emb     = (const float*)d_in[3];
    const float* W1      = (const float*)d_in[4];
    const float* b1      = (const float*)d_in[5];
    const float* W2      = (const float*)d_in[6];
    const float* b2      = (const float*)d_in[7];
    const float* pool_w  = (const float*)d_in[8];
    const float* dense_W = (const float*)d_in[9];
    const float* dense_b = (const float*)d_in[10];
    const float* out_W   = (const float*)d_in[11];
    const float* out_b   = (const float*)d_in[12];
    float* out = (float*)d_out;

    const int TB = 256;
    int gridN  = (NN + TB - 1) / TB;          // node-count grids
    int gridE  = (EE + TB - 1) / TB;          // edge-count grids
    int gridNW = (NN * 32 + TB - 1) / TB;     // warp-per-node grids
    int nScanB = (NN + 1023) / 1024;          // 125

    // CSR build (reused by both layers)
    k_zero_deg<<<gridN, TB>>>();
    k_count_deg<<<gridE, TB>>>(ei);
    k_scan1<<<nScanB, 1024>>>();
    k_scan2<<<1, 128>>>(nScanB);
    k_finalize<<<gridN, TB>>>();
    k_csr_fill<<<gridE, TB>>>(ei);

    // layer 1: project (emb gather fused) then aggregate
    k_proj1<<<gridNW, TB>>>(x, emb, W1);
    k_agg<<<gridNW, TB>>>(b1, pool_w, 0);
    // layer 2: project then aggregate (+ fused score)
    k_proj2<<<gridNW, TB>>>(W2);
    k_agg<<<gridNW, TB>>>(b2, pool_w, 1);

    // per-graph top-K + head
    k_topk_head<<<BB, 1024>>>(dense_W, dense_b, out_W, out_b, out);
}

// round 2
// speedup vs baseline: 1.1459x; 1.1459x over previous
#include <cuda_runtime.h>
#include <cuda_bf16.h>
#include <math.h>

// Problem constants (fixed by the dataset)
#define NN      128000      // nodes = B*NG
#define EE      4096000     // edges = B*EG
#define BB      64          // graphs
#define NG      2000        // nodes per graph
#define KTOP    1600
#define EMB     64
#define G1      32
#define G2      32
#define DENSE   64
#define NCLS    10

// ---------------- device scratch ----------------
__device__ int            g_deg[NN];
__device__ int            g_partial[NN];
__device__ int            g_bsum[256];
__device__ int            g_bbase[256];
__device__ int            g_off[NN + 1];
__device__ unsigned char  g_rank[EE];        // per-edge rank within its dst
__device__ unsigned short g_csr16[EE];       // local (within-graph) src index
__device__ float          g_dinv[NN];
__device__ float          g_bufA[NN * 32];   // proj1 out  /  final h2
__device__ float          g_bufB[NN * 32];   // fused (h1 @ W2) * dinv
__device__ float          g_score[NN];

// ---------------- CSR build ----------------
__global__ void k_zero_deg() {
    int i = blockIdx.x * blockDim.x + threadIdx.x;
    if (i < NN / 4) ((int4*)g_deg)[i] = make_int4(0, 0, 0, 0);
}

// count in-degree; record each edge's rank within its dst (atomic return value)
__global__ void k_count_deg(const int* __restrict__ ei) {
    int i = blockIdx.x * blockDim.x + threadIdx.x;
    if (i >= EE / 4) return;
    int4 d4 = ((const int4*)(ei + EE))[i];
    uchar4 r;
    r.x = (unsigned char)atomicAdd(&g_deg[d4.x], 1);
    r.y = (unsigned char)atomicAdd(&g_deg[d4.y], 1);
    r.z = (unsigned char)atomicAdd(&g_deg[d4.z], 1);
    r.w = (unsigned char)atomicAdd(&g_deg[d4.w], 1);
    ((uchar4*)g_rank)[i] = r;
}

// block-level exclusive scan (1024 elems/block, 125 blocks exactly)
__global__ void k_scan1() {
    __shared__ int s[1024];
    int tid = threadIdx.x;
    int gid = blockIdx.x * 1024 + tid;
    int v = (gid < NN) ? g_deg[gid] : 0;
    int sum = v;
    s[tid] = sum;
    __syncthreads();
    for (int off = 1; off < 1024; off <<= 1) {
        int t = (tid >= off) ? s[tid - off] : 0;
        __syncthreads();
        sum += t;
        s[tid] = sum;
        __syncthreads();
    }
    if (gid < NN) g_partial[gid] = sum - v;
    if (tid == 1023) g_bsum[blockIdx.x] = sum;
}

__global__ void k_scan2(int nblocks) {
    __shared__ int s[128];
    int tid = threadIdx.x;
    int v = (tid < nblocks) ? g_bsum[tid] : 0;
    int sum = v;
    s[tid] = sum;
    __syncthreads();
    for (int off = 1; off < 128; off <<= 1) {
        int t = (tid >= off) ? s[tid - off] : 0;
        __syncthreads();
        sum += t;
        s[tid] = sum;
        __syncthreads();
    }
    if (tid < nblocks) g_bbase[tid] = sum - v;
}

__global__ void k_finalize() {
    int i = blockIdx.x * blockDim.x + threadIdx.x;
    if (i < NN) {
        g_off[i] = g_partial[i] + g_bbase[i >> 10];
        g_dinv[i] = rsqrtf((float)(g_deg[i] + 1));  // +1 self loop
    }
    if (i == 0) g_off[NN] = EE;
}

// atomic-free fill: pos = off[dst] + saved rank; store LOCAL src index as u16
__global__ void k_csr_fill(const int* __restrict__ ei) {
    int i = blockIdx.x * blockDim.x + threadIdx.x;
    if (i >= EE / 4) return;
    int4 s4 = ((const int4*)ei)[i];
    int4 d4 = ((const int4*)(ei + EE))[i];
    uchar4 r = ((const uchar4*)g_rank)[i];
    g_csr16[g_off[d4.x] + r.x] = (unsigned short)(s4.x - (s4.x / NG) * NG);
    g_csr16[g_off[d4.y] + r.y] = (unsigned short)(s4.y - (s4.y / NG) * NG);
    g_csr16[g_off[d4.z] + r.z] = (unsigned short)(s4.z - (s4.z / NG) * NG);
    g_csr16[g_off[d4.w] + r.w] = (unsigned short)(s4.w - (s4.w / NG) * NG);
}

// ---------------- proj1: bufA[n] = dinv[n] * (emb[x[n]] @ W1)  (64 -> 32) ----------------
__global__ void k_proj1(const int* __restrict__ x, const float* __restrict__ emb,
                        const float* __restrict__ W1) {
    __shared__ float Ws[64 * 32];
    int tid = threadIdx.x;
    for (int i = tid; i < 64 * 32; i += blockDim.x) Ws[i] = W1[i];
    __syncthreads();
    int warp = (blockIdx.x * blockDim.x + tid) >> 5;
    int lane = tid & 31;
    if (warp >= NN) return;
    int xi = __ldg(&x[warp]);
    const float* er = emb + (long long)xi * 64;
    float e0 = __ldg(&er[lane]);
    float e1 = __ldg(&er[32 + lane]);
    float acc = 0.f;
#pragma unroll
    for (int k = 0; k < 32; k++)
        acc += __shfl_sync(0xffffffffu, e0, k) * Ws[k * 32 + lane];
#pragma unroll
    for (int k = 0; k < 32; k++)
        acc += __shfl_sync(0xffffffffu, e1, k) * Ws[(32 + k) * 32 + lane];
    g_bufA[warp * 32 + lane] = acc * g_dinv[warp];
}

// ---------------- aggregation core (warp per dst, float4 gathers, 4 edges/iter) --------
// lane l: group g = l>>3 (edge slot), chunk c = l&7 (features 4c..4c+3)
__device__ __forceinline__ float4 warp_gather(const float* __restrict__ buf,
                                              int d, int gbase, int g, int c) {
    float4 acc;
    // self-loop term (buf[d] already premultiplied by dinv[d]); group 0 only
    if (g == 0) acc = *(const float4*)&buf[d * 32 + c * 4];
    else        acc = make_float4(0.f, 0.f, 0.f, 0.f);
    int s0 = g_off[d], s1 = g_off[d + 1];
    int lane = (g << 3) | c;
    for (int e = s0; e < s1; ) {
        int lim = min(s1, e + 32);
        int my = 0;
        if (e + lane < s1) my = (int)g_csr16[e + lane];
        int n = lim - e;
#pragma unroll 4
        for (int t = 0; t * 4 < n; t++) {
            int srcLoc = __shfl_sync(0xffffffffu, my, t * 4 + g);
            if (t * 4 + g < n) {
                float4 v = *(const float4*)&buf[(gbase + srcLoc) * 32 + c * 4];
                acc.x += v.x; acc.y += v.y; acc.z += v.z; acc.w += v.w;
            }
        }
        e = lim;
    }
    // reduce the 4 edge-groups: butterfly over lane bits 3,4
#pragma unroll
    for (int off = 8; off <= 16; off <<= 1) {
        acc.x += __shfl_xor_sync(0xffffffffu, acc.x, off);
        acc.y += __shfl_xor_sync(0xffffffffu, acc.y, off);
        acc.z += __shfl_xor_sync(0xffffffffu, acc.z, off);
        acc.w += __shfl_xor_sync(0xffffffffu, acc.w, off);
    }
    return acc;  // every lane now holds total for features [4c, 4c+4)
}

// layer 1: gather bufA -> h1 = relu(.) -> fused proj2 -> bufB = dinv * (h1 @ W2)
__global__ void k_agg1(const float* __restrict__ b1, const float* __restrict__ W2) {
    __shared__ float W2s[32 * 32];
    int tid = threadIdx.x;
    for (int i = tid; i < 32 * 32; i += blockDim.x) W2s[i] = W2[i];
    __syncthreads();
    int warp = (blockIdx.x * blockDim.x + tid) >> 5;
    if (warp >= NN) return;
    int l = tid & 31, g = l >> 3, c = l & 7;
    int d = warp;
    int gbase = (d / NG) * NG;
    float4 acc = warp_gather(g_bufA, d, gbase, g, c);
    float dv = g_dinv[d];
    float4 bb = *(const float4*)&b1[c * 4];
    float4 h;
    h.x = fmaxf(acc.x * dv + bb.x, 0.f);
    h.y = fmaxf(acc.y * dv + bb.y, 0.f);
    h.z = fmaxf(acc.z * dv + bb.z, 0.f);
    h.w = fmaxf(acc.w * dv + bb.w, 0.f);
    // fused proj2: out[j=l] = dv * sum_k h_k * W2[k][j]
    float hc[4] = {h.x, h.y, h.z, h.w};
    float o = 0.f;
#pragma unroll
    for (int k = 0; k < 32; k++) {
        float hk = __shfl_sync(0xffffffffu, hc[k & 3], k >> 2);
        o += hk * W2s[k * 32 + l];
    }
    g_bufB[d * 32 + l] = o * dv;
}

// layer 2: gather bufB -> h2 = relu(.) -> store bufA + fused score
__global__ void k_agg2(const float* __restrict__ b2, const float* __restrict__ pool_w) {
    int tid = threadIdx.x;
    int warp = (blockIdx.x * blockDim.x + tid) >> 5;
    if (warp >= NN) return;
    int l = tid & 31, g = l >> 3, c = l & 7;
    int d = warp;
    int gbase = (d / NG) * NG;
    float4 acc = warp_gather(g_bufB, d, gbase, g, c);
    float dv = g_dinv[d];
    float4 bb = *(const float4*)&b2[c * 4];
    float4 h;
    h.x = fmaxf(acc.x * dv + bb.x, 0.f);
    h.y = fmaxf(acc.y * dv + bb.y, 0.f);
    h.z = fmaxf(acc.z * dv + bb.z, 0.f);
    h.w = fmaxf(acc.w * dv + bb.w, 0.f);
    if (g == 0) *(float4*)&g_bufA[d * 32 + c * 4] = h;
    // score = tanh(h . pw / ||pw||)
    float4 pw = *(const float4*)&pool_w[c * 4];
    float s  = h.x * pw.x + h.y * pw.y + h.z * pw.z + h.w * pw.w;
    float n2 = pw.x * pw.x + pw.y * pw.y + pw.z * pw.z + pw.w * pw.w;
#pragma unroll
    for (int off = 1; off <= 4; off <<= 1) {
        s  += __shfl_xor_sync(0xffffffffu, s,  off);
        n2 += __shfl_xor_sync(0xffffffffu, n2, off);
    }
    if (l == 0) g_score[d] = tanhf(s * rsqrtf(n2));
}

// ---------------- per-graph top-K + gather-max + MLP head ----------------
__global__ void k_topk_head(const float* __restrict__ dense_W, const float* __restrict__ dense_b,
                            const float* __restrict__ out_W, const float* __restrict__ out_b,
                            float* __restrict__ out) {
    __shared__ unsigned long long keys[2048];
    __shared__ float red[32 * 33];
    __shared__ float gv[32];
    __shared__ float dvs[64];
    int b = blockIdx.x;
    int tid = threadIdx.x;  // 1024 threads

    for (int i = tid; i < 2048; i += 1024) {
        unsigned long long key = 0ull;
        if (i < NG) {
            unsigned u = __float_as_uint(g_score[b * NG + i]);
            u = (u & 0x80000000u) ? ~u : (u | 0x80000000u);
            key = ((unsigned long long)u << 32) | (unsigned long long)(0xFFFFFFFFu - (unsigned)i);
        }
        keys[i] = key;
    }
    __syncthreads();

    for (int k = 2; k <= 2048; k <<= 1) {
        for (int j = k >> 1; j > 0; j >>= 1) {
            for (int i = tid; i < 2048; i += 1024) {
                int ixj = i ^ j;
                if (ixj > i) {
                    bool up = ((i & k) == 0);
                    unsigned long long a = keys[i], cc = keys[ixj];
                    if ((a > cc) == up) { keys[i] = cc; keys[ixj] = a; }
                }
            }
            __syncthreads();
        }
    }

    int j = tid & 31, c = tid >> 5;
    float m = -INFINITY;
    for (int t = c; t < KTOP; t += 32) {
        unsigned long long key = keys[448 + t];
        unsigned up = (unsigned)(key >> 32);
        float val = (up & 0x80000000u) ? __uint_as_float(up ^ 0x80000000u)
                                       : __uint_as_float(~up);
        int idx = (int)(0xFFFFFFFFu - (unsigned)key);
        m = fmaxf(m, g_bufA[(b * NG + idx) * 32 + j] * val);
    }
    red[c * 33 + j] = m;
    __syncthreads();
    if (c == 0) {
        for (int cc = 1; cc < 32; cc++) m = fmaxf(m, red[cc * 33 + j]);
        gv[j] = m;
    }
    __syncthreads();
    if (tid < DENSE) {
        float s = dense_b[tid];
#pragma unroll
        for (int k = 0; k < G2; k++) s += gv[k] * dense_W[k * DENSE + tid];
        dvs[tid] = fmaxf(s, 0.f);
    }
    __syncthreads();
    if (tid < NCLS) {
        float s = out_b[tid];
#pragma unroll
        for (int k = 0; k < DENSE; k++) s += dvs[k] * out_W[k * NCLS + tid];
        out[b * NCLS + tid] = s;
    }
}

// ---------------- launch ----------------
extern "C" void kernel_launch(void* const* d_in, const int* in_sizes, int n_in,
                              void* d_out, int out_size) {
    const int*   x       = (const int*)d_in[0];
    const int*   ei      = (const int*)d_in[1];
    const float* emb     = (const float*)d_in[3];
    const float* W1      = (const float*)d_in[4];
    const float* b1      = (const float*)d_in[5];
    const float* W2      = (const float*)d_in[6];
    const float* b2      = (const float*)d_in[7];
    const float* pool_w  = (const float*)d_in[8];
    const float* dense_W = (const float*)d_in[9];
    const float* dense_b = (const float*)d_in[10];
    const float* out_W   = (const float*)d_in[11];
    const float* out_b   = (const float*)d_in[12];
    float* out = (float*)d_out;

    const int TB = 256;
    int gridN4 = (NN / 4 + TB - 1) / TB;
    int gridN  = (NN + TB - 1) / TB;
    int gridE4 = (EE / 4 + TB - 1) / TB;
    int gridNW = (NN * 32 + TB - 1) / TB;
    int nScanB = (NN + 1023) / 1024;  // 125

    k_zero_deg<<<gridN4, TB>>>();
    k_count_deg<<<gridE4, TB>>>(ei);
    k_scan1<<<nScanB, 1024>>>();
    k_scan2<<<1, 128>>>(nScanB);
    k_finalize<<<gridN, TB>>>();
    k_csr_fill<<<gridE4, TB>>>(ei);

    k_proj1<<<gridNW, TB>>>(x, emb, W1);
    k_agg1<<<gridNW, TB>>>(b1, W2);
    k_agg2<<<gridNW, TB>>>(b2, pool_w);

    k_topk_head<<<BB, 1024>>>(dense_W, dense_b, out_W, out_b, out);
}